// round 14
// baseline (speedup 1.0000x reference)
#include <cuda_runtime.h>
#include <cstdint>

static constexpr int NN = 50000;
static constexpr int EE = 600000;
static constexpr int GG = 64;
static constexpr int HH = 128;
static constexpr int TPB = 256;   // 8 warps: 4 in M (32 rows) x 2 in N (64 cols)

// ---------------- scratch (no allocations allowed) ----------------
__device__ int   d_row[EE];
__device__ int   d_col[EE];
__device__ int   d_batch[NN];
__device__ int   d_is64;
__device__ float d_e_sum[NN * HH];
__device__ float d_cnt[NN];
__device__ float d_e_mean[GG * HH];   // SUM accumulators
__device__ float d_v_mean[GG * HH];   // SUM accumulators
__device__ float d_gecnt[GG];
__device__ int   d_start[GG + 1];
__device__ float d_W1t[HH * 4 * HH];  // [N=128][K] transposed, tf32-rounded
__device__ float d_W2t[HH * HH];
__device__ float d_V1t[HH * 3 * HH];
__device__ float d_V2t[HH * HH];

// ---------------- helpers ----------------
__device__ __forceinline__ uint32_t smem_u32(const void* p) {
    uint32_t a;
    asm("{ .reg .u64 t; cvta.to.shared.u64 t, %1; cvt.u32.u64 %0, t; }" : "=r"(a) : "l"(p));
    return a;
}
__device__ __forceinline__ void ldsm4(uint32_t* r, uint32_t addr) {
    asm volatile("ldmatrix.sync.aligned.m8n8.x4.shared.b16 {%0,%1,%2,%3}, [%4];"
        : "=r"(r[0]), "=r"(r[1]), "=r"(r[2]), "=r"(r[3]) : "r"(addr));
}
__device__ __forceinline__ void mma_tf32(float* c, const uint32_t* a, uint32_t b0, uint32_t b1) {
    asm volatile("mma.sync.aligned.m16n8k8.row.col.f32.tf32.tf32.f32 "
        "{%0,%1,%2,%3}, {%4,%5,%6,%7}, {%8,%9}, {%0,%1,%2,%3};"
        : "+f"(c[0]), "+f"(c[1]), "+f"(c[2]), "+f"(c[3])
        : "r"(a[0]), "r"(a[1]), "r"(a[2]), "r"(a[3]), "r"(b0), "r"(b1));
}
__device__ __forceinline__ float tf32r(float v) {
    uint32_t r;
    asm("cvt.rna.tf32.f32 %0, %1;" : "=r"(r) : "f"(v));
    return __uint_as_float(r);
}
__device__ __forceinline__ uint32_t tf32u(float v) {
    uint32_t r;
    asm("cvt.rna.tf32.f32 %0, %1;" : "=r"(r) : "f"(v));
    return r;
}
__device__ __forceinline__ void cpa16(uint32_t dst, const void* src) {
    asm volatile("cp.async.cg.shared.global [%0], [%1], 16;" :: "r"(dst), "l"(src));
}
#define CP_COMMIT() asm volatile("cp.async.commit_group;" ::: "memory")
#define CP_WAIT0()  asm volatile("cp.async.wait_group 0;" ::: "memory")
__device__ __forceinline__ float softplusf(float v) {
    float t = __expf(-fabsf(v));
    return fmaxf(v, 0.0f) + __logf(1.0f + t);
}

// ---------------- prep kernels ----------------
__global__ void detect_kernel(const int* __restrict__ ei) {
    if (threadIdx.x == 0) {
        int all0 = 1;
        for (int i = 0; i < 64; ++i)
            if (ei[2 * i + 1] != 0) { all0 = 0; break; }
        d_is64 = all0;
    }
}
__global__ void convert_zero_kernel(const int* __restrict__ ei, const int* __restrict__ batch) {
    int i = blockIdx.x * 256 + threadIdx.x;
    int is64 = d_is64;
    if (i < EE) {
        d_row[i] = is64 ? ei[2 * i]          : ei[i];
        d_col[i] = is64 ? ei[2 * EE + 2 * i] : ei[EE + i];
    }
    if (i < NN) {
        d_batch[i] = is64 ? batch[2 * i] : batch[i];
        d_cnt[i] = 0.0f;
    }
    if (i < NN * HH) d_e_sum[i] = 0.0f;
    if (i < GG * HH) { d_e_mean[i] = 0.0f; d_v_mean[i] = 0.0f; }
    if (i < GG) d_gecnt[i] = 0.0f;
}
__global__ void prep_all_kernel(const float* __restrict__ We1, const float* __restrict__ We2,
                                const float* __restrict__ Wv1, const float* __restrict__ Wv2) {
    int i = blockIdx.x * 256 + threadIdx.x;
    if (i < 4 * HH * HH) {
        int k = i / HH, n = i % HH;
        d_W1t[n * (4 * HH) + k] = tf32r(We1[i]);
    }
    if (i < 3 * HH * HH) {
        int k = i / HH, n = i % HH;
        d_V1t[n * (3 * HH) + k] = tf32r(Wv1[i]);
    }
    if (i < HH * HH) {
        int k = i / HH, n = i % HH;
        d_W2t[n * HH + k] = tf32r(We2[i]);
        d_V2t[n * HH + k] = tf32r(Wv2[i]);
    }
}
__global__ void seg_starts_kernel() {
    int v = blockIdx.x * 256 + threadIdx.x;
    if (v >= NN) return;
    int b = d_batch[v];
    int bp = (v == 0) ? -1 : d_batch[v - 1];
    for (int g = bp + 1; g <= b; ++g) d_start[g] = v;
    if (v == NN - 1)
        for (int g = b + 1; g <= GG; ++g) d_start[g] = NN;
}

// ---------------- fused 2-layer MLP, tf32 mma.sync, A direct-from-global ----------------
// EDGE: in = [x[row], x[col], edge_attr, u[batch[row]]] (K=512), + scatter
// NODE: in = [x, e_sum*rc, u[batch]]                    (K=384)
// Warp tiling: 4M (32 rows) x 2N (64 cols). A fragments gathered straight from
// GMEM into registers (no smem staging/ldsm for A). B double-buffered via cp.async.
// Dynamic smem (90624 B): base(2048) sRC(512) sB[2](20480 @2560) sH1(67584 @23040)
template<int NSEG, bool EDGE>
__global__ void __launch_bounds__(TPB, 2)
mlp2_mma(const float* __restrict__ s0, const float* __restrict__ s1,
         const float* __restrict__ s2, const float* __restrict__ s3,
         const float* __restrict__ W1t, const float* __restrict__ b1,
         const float* __restrict__ W2t, const float* __restrict__ b2,
         float* __restrict__ outp, int M)
{
    extern __shared__ char sm[];
    int* base = (int*)sm;
    float* sRC = (float*)(sm + 2048);
    char* sB0 = sm + 2560;
    char* sH1 = sm + 23040;
    const uint32_t aB = smem_u32(sB0), aH1 = smem_u32(sH1);

    const int tid = threadIdx.x;
    const int w = tid >> 5, l = tid & 31;
    const int mg = w & 3, ng = w >> 2;          // 4 M-groups x 2 N-groups
    const int m0 = blockIdx.x * 128;

    if (tid < 128) {
        int r = m0 + tid;
        int b0 = 0, b1_ = 0, b2_ = 0, b3_ = 0;
        float rc = 1.0f;
        if (r < M) {
            if (EDGE) {
                int row = d_row[r];
                b0 = row * HH;
                b1_ = d_col[r] * HH;
                b2_ = r * HH;
                b3_ = d_batch[row] * HH;
            } else {
                b0 = r * HH;
                b1_ = r * HH;
                b2_ = d_batch[r] * HH;
                rc = 1.0f / fmaxf(d_cnt[r], 1.0f);
            }
        }
        base[tid * 4 + 0] = b0; base[tid * 4 + 1] = b1_;
        base[tid * 4 + 2] = b2_; base[tid * 4 + 3] = b3_;
        if (!EDGE) sRC[tid] = rc;
    }
    __syncthreads();

    const int row = tid >> 1, half = tid & 1;   // B staging assignment
    const int K1 = NSEG * 128;
    const int NCH = NSEG * 8;
    const uint32_t stg = (uint32_t)(row * 80 + half * 32);

    // ldmatrix lane offsets (sB rows 80B, sH1 rows 528B)
    const uint32_t boffW = (uint32_t)(((l & 7) + ((l >> 4) & 1) * 8) * 80 + ((l >> 3) & 1) * 16
                                      + 64 * ng * 80);
    const uint32_t hoff0 = (uint32_t)((32 * mg + (l & 15)) * 528 + (l >> 4) * 16);
    const uint32_t hoff1 = hoff0 + 16 * 528;

    float acc[2][8][4];
    #pragma unroll
    for (int t = 0; t < 2; ++t)
        #pragma unroll
        for (int j = 0; j < 8; ++j)
            #pragma unroll
            for (int q = 0; q < 4; ++q) acc[t][j][q] = 0.0f;

    const float* sptr[4];
    sptr[0] = s0;
    sptr[1] = EDGE ? s1 : d_e_sum;
    sptr[2] = s2;
    sptr[3] = (NSEG == 4) ? s3 : s2;

    // per-thread fragment rows (local): 32*mg + l/4 + {0,8,16,24}
    const int fr = 32 * mg + (l >> 2);
    const int fc = (l & 3);                     // fragment col within k8

    // MMA for one chunk: A fragments in au[t][j][4], B from buffer bo
    auto mmachunk = [&](uint32_t bo, const uint32_t au[2][2][4]) {
        #pragma unroll
        for (int p = 0; p < 4; ++p) {
            uint32_t b[4], b2[4];
            ldsm4(b,  aB + bo + boffW + p * 1280);        // n8 tiles 2p,2p+1, k8#0
            ldsm4(b2, aB + bo + boffW + p * 1280 + 32);   // k8#1
            mma_tf32(acc[0][2 * p],     au[0][0], b[0],  b[1]);
            mma_tf32(acc[0][2 * p + 1], au[0][0], b[2],  b[3]);
            mma_tf32(acc[1][2 * p],     au[1][0], b[0],  b[1]);
            mma_tf32(acc[1][2 * p + 1], au[1][0], b[2],  b[3]);
            mma_tf32(acc[0][2 * p],     au[0][1], b2[0], b2[1]);
            mma_tf32(acc[0][2 * p + 1], au[0][1], b2[2], b2[3]);
            mma_tf32(acc[1][2 * p],     au[1][1], b2[0], b2[1]);
            mma_tf32(acc[1][2 * p + 1], au[1][1], b2[2], b2[3]);
        }
    };

    // B(0) cp.async
    {
        const float* bp = W1t + row * K1 + half * 8;
        cpa16(aB + stg, bp);
        cpa16(aB + stg + 16, bp + 4);
        CP_COMMIT();
    }

    // ---------------- layer 1: seg-major, A direct from global ----------------
    #pragma unroll 1
    for (int seg = 0; seg < NSEG; ++seg) {
        const float* sp = sptr[seg];
        // 4 row bases for this seg (regs)
        const int rb0 = base[(fr +  0) * 4 + seg];
        const int rb1 = base[(fr +  8) * 4 + seg];
        const int rb2 = base[(fr + 16) * 4 + seg];
        const int rb3 = base[(fr + 24) * 4 + seg];
        // per-row scale (NODE seg 1 only)
        float sc0 = 1.0f, sc1 = 1.0f, sc2 = 1.0f, sc3 = 1.0f;
        if (!EDGE && seg == 1) {
            sc0 = sRC[fr]; sc1 = sRC[fr + 8]; sc2 = sRC[fr + 16]; sc3 = sRC[fr + 24];
        }
        // fragment load for local chunk cc: cur[t][j][q]
        auto loadF = [&](int cc, float f[2][2][4]) {
            int c0 = cc * 16 + fc;
            #pragma unroll
            for (int j = 0; j < 2; ++j) {
                int k = c0 + 8 * j;
                f[0][j][0] = sp[rb0 + k];
                f[0][j][1] = sp[rb1 + k];
                f[0][j][2] = sp[rb0 + k + 4];
                f[0][j][3] = sp[rb1 + k + 4];
                f[1][j][0] = sp[rb2 + k];
                f[1][j][1] = sp[rb3 + k];
                f[1][j][2] = sp[rb2 + k + 4];
                f[1][j][3] = sp[rb3 + k + 4];
            }
        };
        float cur[2][2][4], nxt[2][2][4];
        loadF(0, cur);

        #pragma unroll 1
        for (int cc = 0; cc < 8; ++cc) {
            const int c = seg * 8 + cc;                  // global chunk index
            const uint32_t bo = (uint32_t)((c & 1) * 10240);
            if (cc < 7) loadF(cc + 1, nxt);              // 1-deep A prefetch
            CP_WAIT0();                                  // B(c) landed
            __syncthreads();
            if (c + 1 < NCH) {                           // B(c+1) into other buffer
                const float* bp = W1t + row * K1 + (c + 1) * 16 + half * 8;
                cpa16(aB + (bo ^ 10240) + stg, bp);
                cpa16(aB + (bo ^ 10240) + stg + 16, bp + 4);
            }
            CP_COMMIT();
            // cvt fragments (scaled) to tf32
            uint32_t au[2][2][4];
            #pragma unroll
            for (int j = 0; j < 2; ++j) {
                au[0][j][0] = tf32u(cur[0][j][0] * sc0);
                au[0][j][1] = tf32u(cur[0][j][1] * sc1);
                au[0][j][2] = tf32u(cur[0][j][2] * sc0);
                au[0][j][3] = tf32u(cur[0][j][3] * sc1);
                au[1][j][0] = tf32u(cur[1][j][0] * sc2);
                au[1][j][1] = tf32u(cur[1][j][1] * sc3);
                au[1][j][2] = tf32u(cur[1][j][2] * sc2);
                au[1][j][3] = tf32u(cur[1][j][3] * sc3);
            }
            mmachunk(bo, au);
            #pragma unroll
            for (int t = 0; t < 2; ++t)
                #pragma unroll
                for (int j = 0; j < 2; ++j)
                    #pragma unroll
                    for (int q = 0; q < 4; ++q) cur[t][j][q] = nxt[t][j][q];
        }
    }

    // W2(0) cp.async early (layer-1 ended on odd chunk -> buffer 0 free)
    {
        const float* bp = W2t + row * 128 + half * 8;
        cpa16(aB + stg, bp);
        cpa16(aB + stg + 16, bp + 4);
        CP_COMMIT();
    }

    // ---------------- layer-1 epilogue: bias + softplus -> sH1 ----------------
    #pragma unroll
    for (int t = 0; t < 2; ++t) {
        const int r0 = 32 * mg + 16 * t + (l >> 2);
        #pragma unroll
        for (int j = 0; j < 8; ++j) {
            int col = 64 * ng + j * 8 + 2 * (l & 3);
            float bb0 = __ldg(b1 + col), bb1 = __ldg(b1 + col + 1);
            float h00 = tf32r(softplusf(acc[t][j][0] + bb0));
            float h01 = tf32r(softplusf(acc[t][j][1] + bb1));
            float h10 = tf32r(softplusf(acc[t][j][2] + bb0));
            float h11 = tf32r(softplusf(acc[t][j][3] + bb1));
            *(float2*)(sH1 + r0 * 528 + col * 4)       = make_float2(h00, h01);
            *(float2*)(sH1 + (r0 + 8) * 528 + col * 4) = make_float2(h10, h11);
            acc[t][j][0] = acc[t][j][1] = acc[t][j][2] = acc[t][j][3] = 0.0f;
        }
    }

    // ---------------- layer 2: K=128, 8 chunks (h1 via ldsm from sH1) ----------------
    const uint32_t hoffs[2] = { hoff0, hoff1 };
    for (int c = 0; c < 8; ++c) {
        const uint32_t boffs = (uint32_t)((c & 1) * 10240);
        CP_WAIT0();
        __syncthreads();              // first iter: also orders sH1 stores before ldsm
        if (c + 1 < 8) {
            const float* bp = W2t + row * 128 + (c + 1) * 16 + half * 8;
            cpa16(aB + (boffs ^ 10240) + stg, bp);
            cpa16(aB + (boffs ^ 10240) + stg + 16, bp + 4);
        }
        CP_COMMIT();

        const int k0 = c * 16;
        uint32_t au[2][2][4];
        ldsm4(au[0][0], aH1 + hoffs[0] + k0 * 4);
        ldsm4(au[0][1], aH1 + hoffs[0] + k0 * 4 + 32);
        ldsm4(au[1][0], aH1 + hoffs[1] + k0 * 4);
        ldsm4(au[1][1], aH1 + hoffs[1] + k0 * 4 + 32);
        mmachunk(boffs, au);
    }

    // ---------------- epilogue 2: bias + softplus + store (+ scatter) ----------------
    #pragma unroll
    for (int t = 0; t < 2; ++t) {
        const int r0l = 32 * mg + 16 * t + (l >> 2);
        const int r0 = m0 + r0l;
        const int db0 = EDGE ? base[r0l * 4 + 0] : 0;
        const int db1 = EDGE ? base[(r0l + 8) * 4 + 0] : 0;
        #pragma unroll
        for (int j = 0; j < 8; ++j) {
            int col = 64 * ng + j * 8 + 2 * (l & 3);
            float bb0 = __ldg(b2 + col), bb1 = __ldg(b2 + col + 1);
            float o00 = softplusf(acc[t][j][0] + bb0);
            float o01 = softplusf(acc[t][j][1] + bb1);
            float o10 = softplusf(acc[t][j][2] + bb0);
            float o11 = softplusf(acc[t][j][3] + bb1);
            if (r0 < M) {
                *(float2*)(outp + (size_t)r0 * HH + col) = make_float2(o00, o01);
                if (EDGE) {
                    atomicAdd(&d_e_sum[db0 + col], o00);
                    atomicAdd(&d_e_sum[db0 + col + 1], o01);
                }
            }
            if (r0 + 8 < M) {
                *(float2*)(outp + (size_t)(r0 + 8) * HH + col) = make_float2(o10, o11);
                if (EDGE) {
                    atomicAdd(&d_e_sum[db1 + col], o10);
                    atomicAdd(&d_e_sum[db1 + col + 1], o11);
                }
            }
        }
        if (EDGE && ng == 0 && (l & 3) == 0) {   // rows shared by 2 warps: count once
            if (r0 < M)     atomicAdd(&d_cnt[db0 >> 7], 1.0f);
            if (r0 + 8 < M) atomicAdd(&d_cnt[db1 >> 7], 1.0f);
        }
    }
}

// ---------------- per-graph partial reductions (grid: GG x NSPLIT) ----------------
static constexpr int NSPLIT = 8;
__global__ void graph_partial_kernel(const float* __restrict__ xnew) {
    int g = blockIdx.x;
    int n = threadIdx.x;
    int s = d_start[g], e = d_start[g + 1];
    int len = e - s;
    int per = (len + NSPLIT - 1) / NSPLIT;
    int ls = s + blockIdx.y * per;
    int le = min(ls + per, e);
    if (ls >= le) return;
    float se = 0.0f, sv = 0.0f;
    for (int v = ls; v < le; ++v) {
        se += d_e_sum[v * HH + n];
        sv += xnew[(size_t)v * HH + n];
    }
    atomicAdd(&d_e_mean[g * HH + n], se);
    atomicAdd(&d_v_mean[g * HH + n], sv);
    __shared__ float red[HH];
    float sc = 0.0f;
    for (int v = ls + n; v < le; v += HH) sc += d_cnt[v];
    red[n] = sc;
    __syncthreads();
    for (int off = 64; off > 0; off >>= 1) {
        if (n < off) red[n] += red[n + off];
        __syncthreads();
    }
    if (n == 0) atomicAdd(&d_gecnt[g], red[0]);
}

__global__ void global_mlp_kernel(const float* __restrict__ u,
                                  const float* __restrict__ W1, const float* __restrict__ b1,
                                  const float* __restrict__ W2, const float* __restrict__ b2,
                                  float* __restrict__ out_u) {
    __shared__ float in[3 * HH];
    __shared__ float h1s[HH];
    int g = blockIdx.x, n = threadIdx.x;
    float ec = fmaxf(d_gecnt[g], 1.0f);
    float vc = fmaxf((float)(d_start[g + 1] - d_start[g]), 1.0f);
    in[n]          = u[g * HH + n];
    in[HH + n]     = d_e_mean[g * HH + n] / ec;
    in[2 * HH + n] = d_v_mean[g * HH + n] / vc;
    __syncthreads();
    float a = b1[n];
    for (int k = 0; k < 3 * HH; ++k) a += in[k] * W1[k * HH + n];
    h1s[n] = softplusf(a);
    __syncthreads();
    float o = b2[n];
    for (int k = 0; k < HH; ++k) o += h1s[k] * W2[k * HH + n];
    out_u[g * HH + n] = softplusf(o);
}

// ---------------- launch ----------------
extern "C" void kernel_launch(void* const* d_in, const int* in_sizes, int n_in,
                              void* d_out, int out_size) {
    const float* x     = (const float*)d_in[0];
    const int*   ei    = (const int*)d_in[1];
    const float* ea    = (const float*)d_in[2];
    const float* u     = (const float*)d_in[3];
    const int*   batch = (const int*)d_in[4];
    const float* We1 = (const float*)d_in[5];
    const float* be1 = (const float*)d_in[6];
    const float* We2 = (const float*)d_in[7];
    const float* be2 = (const float*)d_in[8];
    const float* Wv1 = (const float*)d_in[9];
    const float* bv1 = (const float*)d_in[10];
    const float* Wv2 = (const float*)d_in[11];
    const float* bv2 = (const float*)d_in[12];
    const float* Wu1 = (const float*)d_in[13];
    const float* bu1 = (const float*)d_in[14];
    const float* Wu2 = (const float*)d_in[15];
    const float* bu2 = (const float*)d_in[16];

    float* out   = (float*)d_out;
    float* out_x = out;
    float* out_e = out + (size_t)NN * HH;
    float* out_u = out + (size_t)(NN + EE) * HH;

    float *pW1t, *pW2t, *pV1t, *pV2t;
    cudaGetSymbolAddress((void**)&pW1t, d_W1t);
    cudaGetSymbolAddress((void**)&pW2t, d_W2t);
    cudaGetSymbolAddress((void**)&pV1t, d_V1t);
    cudaGetSymbolAddress((void**)&pV2t, d_V2t);

    const int SMEM = 90624;
    cudaFuncSetAttribute(mlp2_mma<4, true>,  cudaFuncAttributeMaxDynamicSharedMemorySize, SMEM);
    cudaFuncSetAttribute(mlp2_mma<3, false>, cudaFuncAttributeMaxDynamicSharedMemorySize, SMEM);

    detect_kernel<<<1, 32>>>(ei);
    convert_zero_kernel<<<(NN * HH + 255) / 256, 256>>>(ei, batch);
    prep_all_kernel<<<(4 * HH * HH + 255) / 256, 256>>>(We1, We2, Wv1, Wv2);

    // edge MLP + scatter (4th launch: ncu capture window)
    mlp2_mma<4, true><<<(EE + 127) / 128, TPB, SMEM>>>(
        x, x, ea, u, pW1t, be1, pW2t, be2, out_e, EE);

    // node MLP (e_aggr on the fly)
    mlp2_mma<3, false><<<(NN + 127) / 128, TPB, SMEM>>>(
        x, nullptr, u, nullptr, pV1t, bv1, pV2t, bv2, out_x, NN);

    seg_starts_kernel<<<(NN + 255) / 256, 256>>>();
    graph_partial_kernel<<<dim3(GG, NSPLIT), HH>>>(out_x);
    global_mlp_kernel<<<GG, HH>>>(u, Wu1, bu1, Wu2, bu2, out_u);
}

// round 15
// speedup vs baseline: 1.2164x; 1.2164x over previous
#include <cuda_runtime.h>
#include <cstdint>

static constexpr int NN = 50000;
static constexpr int EE = 600000;
static constexpr int GG = 64;
static constexpr int HH = 128;
static constexpr int TPB = 256;   // 8 warps: 4 in M (32 rows) x 2 in N (64 cols)

// ---------------- scratch (no allocations allowed) ----------------
__device__ int   d_row[EE];
__device__ int   d_col[EE];
__device__ int   d_batch[NN];
__device__ int   d_is64;
__device__ float d_e_sum[NN * HH];
__device__ float d_cnt[NN];
__device__ float d_e_mean[GG * HH];   // SUM accumulators
__device__ float d_v_mean[GG * HH];   // SUM accumulators
__device__ float d_gecnt[GG];
__device__ int   d_start[GG + 1];
__device__ float d_W1t[HH * 4 * HH];  // [N=128][K] transposed, tf32-rounded
__device__ float d_W2t[HH * HH];
__device__ float d_V1t[HH * 3 * HH];
__device__ float d_V2t[HH * HH];

// ---------------- helpers ----------------
__device__ __forceinline__ uint32_t smem_u32(const void* p) {
    uint32_t a;
    asm("{ .reg .u64 t; cvta.to.shared.u64 t, %1; cvt.u32.u64 %0, t; }" : "=r"(a) : "l"(p));
    return a;
}
__device__ __forceinline__ void ldsm4(uint32_t* r, uint32_t addr) {
    asm volatile("ldmatrix.sync.aligned.m8n8.x4.shared.b16 {%0,%1,%2,%3}, [%4];"
        : "=r"(r[0]), "=r"(r[1]), "=r"(r[2]), "=r"(r[3]) : "r"(addr));
}
__device__ __forceinline__ void mma_tf32(float* c, const uint32_t* a, uint32_t b0, uint32_t b1) {
    asm volatile("mma.sync.aligned.m16n8k8.row.col.f32.tf32.tf32.f32 "
        "{%0,%1,%2,%3}, {%4,%5,%6,%7}, {%8,%9}, {%0,%1,%2,%3};"
        : "+f"(c[0]), "+f"(c[1]), "+f"(c[2]), "+f"(c[3])
        : "r"(a[0]), "r"(a[1]), "r"(a[2]), "r"(a[3]), "r"(b0), "r"(b1));
}
__device__ __forceinline__ float tf32r(float v) {
    uint32_t r;
    asm("cvt.rna.tf32.f32 %0, %1;" : "=r"(r) : "f"(v));
    return __uint_as_float(r);
}
__device__ __forceinline__ float4 tf32r4s(float4 v, float s) {
    return make_float4(tf32r(v.x * s), tf32r(v.y * s), tf32r(v.z * s), tf32r(v.w * s));
}
__device__ __forceinline__ void cpa16(uint32_t dst, const void* src) {
    asm volatile("cp.async.cg.shared.global [%0], [%1], 16;" :: "r"(dst), "l"(src));
}
#define CP_COMMIT() asm volatile("cp.async.commit_group;" ::: "memory")
#define CP_WAIT0()  asm volatile("cp.async.wait_group 0;" ::: "memory")
__device__ __forceinline__ float softplusf(float v) {
    float t = __expf(-fabsf(v));
    return fmaxf(v, 0.0f) + __logf(1.0f + t);
}

// ---------------- prep kernels ----------------
__global__ void detect_kernel(const int* __restrict__ ei) {
    if (threadIdx.x == 0) {
        int all0 = 1;
        for (int i = 0; i < 64; ++i)
            if (ei[2 * i + 1] != 0) { all0 = 0; break; }
        d_is64 = all0;
    }
}
__global__ void convert_zero_kernel(const int* __restrict__ ei, const int* __restrict__ batch) {
    int i = blockIdx.x * 256 + threadIdx.x;
    int is64 = d_is64;
    if (i < EE) {
        d_row[i] = is64 ? ei[2 * i]          : ei[i];
        d_col[i] = is64 ? ei[2 * EE + 2 * i] : ei[EE + i];
    }
    if (i < NN) {
        d_batch[i] = is64 ? batch[2 * i] : batch[i];
        d_cnt[i] = 0.0f;
    }
    if (i < NN * HH) d_e_sum[i] = 0.0f;
    if (i < GG * HH) { d_e_mean[i] = 0.0f; d_v_mean[i] = 0.0f; }
    if (i < GG) d_gecnt[i] = 0.0f;
}
__global__ void prep_all_kernel(const float* __restrict__ We1, const float* __restrict__ We2,
                                const float* __restrict__ Wv1, const float* __restrict__ Wv2) {
    int i = blockIdx.x * 256 + threadIdx.x;
    if (i < 4 * HH * HH) {
        int k = i / HH, n = i % HH;
        d_W1t[n * (4 * HH) + k] = tf32r(We1[i]);
    }
    if (i < 3 * HH * HH) {
        int k = i / HH, n = i % HH;
        d_V1t[n * (3 * HH) + k] = tf32r(Wv1[i]);
    }
    if (i < HH * HH) {
        int k = i / HH, n = i % HH;
        d_W2t[n * HH + k] = tf32r(We2[i]);
        d_V2t[n * HH + k] = tf32r(Wv2[i]);
    }
}
__global__ void seg_starts_kernel() {
    int v = blockIdx.x * 256 + threadIdx.x;
    if (v >= NN) return;
    int b = d_batch[v];
    int bp = (v == 0) ? -1 : d_batch[v - 1];
    for (int g = bp + 1; g <= b; ++g) d_start[g] = v;
    if (v == NN - 1)
        for (int g = b + 1; g <= GG; ++g) d_start[g] = NN;
}

// ---------------- fused 2-layer MLP, tf32 mma.sync, 4Mx2N warp tiling ----------------
// EDGE: in = [x[row], x[col], edge_attr, u[batch[row]]] (K=512), + scatter
//       A gathered DIRECTLY into smem via cp.async (tensor core truncates fp32->tf32)
// NODE: in = [x, e_sum*rc, u[batch]] (K=384), A staged via registers with rna rounding
// Dynamic smem (111104 B): base(2048) sRC(512) sA[2](20480 @2560) sB[2](20480 @23040)
//                          sH1(67584 @43520)
template<int NSEG, bool EDGE>
__global__ void __launch_bounds__(TPB, 2)
mlp2_mma(const float* __restrict__ s0, const float* __restrict__ s1,
         const float* __restrict__ s2, const float* __restrict__ s3,
         const float* __restrict__ W1t, const float* __restrict__ b1,
         const float* __restrict__ W2t, const float* __restrict__ b2,
         float* __restrict__ outp, int M)
{
    extern __shared__ char sm[];
    int* base = (int*)sm;
    float* sRC = (float*)(sm + 2048);
    char* sA0 = sm + 2560;
    char* sB0 = sm + 23040;
    char* sH1 = sm + 43520;
    const uint32_t aA = smem_u32(sA0), aB = smem_u32(sB0), aH1 = smem_u32(sH1);

    const int tid = threadIdx.x;
    const int w = tid >> 5, l = tid & 31;
    const int mg = w & 3, ng = w >> 2;          // 4 M-groups x 2 N-groups
    const int m0 = blockIdx.x * 128;

    if (tid < 128) {
        int r = m0 + tid;
        int b0 = 0, b1_ = 0, b2_ = 0, b3_ = 0;
        float rc = 1.0f;
        if (r < M) {
            if (EDGE) {
                int row = d_row[r];
                b0 = row * HH;
                b1_ = d_col[r] * HH;
                b2_ = r * HH;
                b3_ = d_batch[row] * HH;
            } else {
                b0 = r * HH;
                b1_ = r * HH;
                b2_ = d_batch[r] * HH;
                rc = 1.0f / fmaxf(d_cnt[r], 1.0f);
            }
        }
        base[tid * 4 + 0] = b0; base[tid * 4 + 1] = b1_;
        base[tid * 4 + 2] = b2_; base[tid * 4 + 3] = b3_;
        if (!EDGE) sRC[tid] = rc;
    }
    __syncthreads();

    const int row = tid >> 1, half = tid & 1;   // staging: 8 floats per thread
    const int K1 = NSEG * 128;
    const int NCH = NSEG * 8;
    const uint32_t stg = (uint32_t)(row * 80 + half * 32);

    // ldmatrix lane offsets (sA/sB rows 80B, sH1 rows 528B)
    const uint32_t aoff0 = (uint32_t)((32 * mg + (l & 15)) * 80 + (l >> 4) * 16);
    const uint32_t aoff1 = aoff0 + 16 * 80;
    const uint32_t boffW = (uint32_t)(((l & 7) + ((l >> 4) & 1) * 8) * 80 + ((l >> 3) & 1) * 16
                                      + 64 * ng * 80);
    const uint32_t hoff0 = (uint32_t)((32 * mg + (l & 15)) * 528 + (l >> 4) * 16);
    const uint32_t hoff1 = hoff0 + 16 * 528;

    float acc[2][8][4];
    #pragma unroll
    for (int t = 0; t < 2; ++t)
        #pragma unroll
        for (int j = 0; j < 8; ++j)
            #pragma unroll
            for (int q = 0; q < 4; ++q) acc[t][j][q] = 0.0f;

    const float* sptr[4];
    sptr[0] = s0;
    sptr[1] = EDGE ? s1 : d_e_sum;
    sptr[2] = s2;
    sptr[3] = (NSEG == 4) ? s3 : s2;

    // gather source pointer for chunk c (this thread's 32B slice)
    auto asrc = [&](int c) -> const float* {
        int k0 = c * 16;
        int sg = k0 >> 7;
        return sptr[sg] + base[row * 4 + sg] + (k0 & 127) + half * 8;
    };
    auto segscale = [&](int c) -> float {
        return (!EDGE && ((c * 16) >> 7) == 1) ? sRC[row] : 1.0f;
    };
    // MMA for one chunk: A via ldsm from sA buffer bo, B via ldsm from sB buffer bo
    auto mmachunk = [&](uint32_t bo) {
        uint32_t a00[4], a01[4], a10[4], a11[4];
        ldsm4(a00, aA + bo + aoff0);
        ldsm4(a01, aA + bo + aoff0 + 32);
        ldsm4(a10, aA + bo + aoff1);
        ldsm4(a11, aA + bo + aoff1 + 32);
        #pragma unroll
        for (int p = 0; p < 4; ++p) {
            uint32_t b[4], b2[4];
            ldsm4(b,  aB + bo + boffW + p * 1280);        // n8 tiles 2p,2p+1, k8#0
            ldsm4(b2, aB + bo + boffW + p * 1280 + 32);   // k8#1
            mma_tf32(acc[0][2 * p],     a00, b[0],  b[1]);
            mma_tf32(acc[0][2 * p + 1], a00, b[2],  b[3]);
            mma_tf32(acc[1][2 * p],     a10, b[0],  b[1]);
            mma_tf32(acc[1][2 * p + 1], a10, b[2],  b[3]);
            mma_tf32(acc[0][2 * p],     a01, b2[0], b2[1]);
            mma_tf32(acc[0][2 * p + 1], a01, b2[2], b2[3]);
            mma_tf32(acc[1][2 * p],     a11, b2[0], b2[1]);
            mma_tf32(acc[1][2 * p + 1], a11, b2[2], b2[3]);
        }
    };

    // ---------------- layer 1 prologue ----------------
    float4 fA0, fA1;
    if (EDGE) {
        // A(0) + B(0) via cp.async into buffer 0
        const float* ap = asrc(0);
        cpa16(aA + stg, ap);
        cpa16(aA + stg + 16, ap + 4);
        const float* bp = W1t + row * K1 + half * 8;
        cpa16(aB + stg, bp);
        cpa16(aB + stg + 16, bp + 4);
        CP_COMMIT();
    } else {
        const float* ap = asrc(0);
        fA0 = *(const float4*)ap;
        fA1 = *(const float4*)(ap + 4);
        const float* bp = W1t + row * K1 + half * 8;
        cpa16(aB + stg, bp);
        cpa16(aB + stg + 16, bp + 4);
        CP_COMMIT();
    }

    // ---------------- layer 1: 1 barrier per chunk ----------------
    #pragma unroll 1
    for (int c = 0; c < NCH; ++c) {
        const uint32_t bo = (uint32_t)((c & 1) * 10240);
        if (!EDGE) {
            // stage A(c) with rna rounding (+1/cnt scale for seg 1)
            float sc = segscale(c);
            *(float4*)(sA0 + bo + stg)      = tf32r4s(fA0, sc);
            *(float4*)(sA0 + bo + stg + 16) = tf32r4s(fA1, sc);
            if (c + 1 < NCH) {               // 1-deep register prefetch
                const float* ap = asrc(c + 1);
                fA0 = *(const float4*)ap;
                fA1 = *(const float4*)(ap + 4);
            }
        }
        CP_WAIT0();                          // A(c) (EDGE) and B(c) landed
        __syncthreads();
        if (c + 1 < NCH) {                   // next chunk into other buffer
            if (EDGE) {
                const float* ap = asrc(c + 1);
                cpa16(aA + (bo ^ 10240) + stg, ap);
                cpa16(aA + (bo ^ 10240) + stg + 16, ap + 4);
            }
            const float* bp = W1t + row * K1 + (c + 1) * 16 + half * 8;
            cpa16(aB + (bo ^ 10240) + stg, bp);
            cpa16(aB + (bo ^ 10240) + stg + 16, bp + 4);
        }
        CP_COMMIT();
        mmachunk(bo);
    }

    // W2(0) cp.async early (layer-1 ended on odd chunk -> buffer 0 free)
    {
        const float* bp = W2t + row * 128 + half * 8;
        cpa16(aB + stg, bp);
        cpa16(aB + stg + 16, bp + 4);
        CP_COMMIT();
    }

    // ---------------- layer-1 epilogue: bias + softplus -> sH1 (rna) ----------------
    #pragma unroll
    for (int t = 0; t < 2; ++t) {
        const int r0 = 32 * mg + 16 * t + (l >> 2);
        #pragma unroll
        for (int j = 0; j < 8; ++j) {
            int col = 64 * ng + j * 8 + 2 * (l & 3);
            float bb0 = __ldg(b1 + col), bb1 = __ldg(b1 + col + 1);
            float h00 = tf32r(softplusf(acc[t][j][0] + bb0));
            float h01 = tf32r(softplusf(acc[t][j][1] + bb1));
            float h10 = tf32r(softplusf(acc[t][j][2] + bb0));
            float h11 = tf32r(softplusf(acc[t][j][3] + bb1));
            *(float2*)(sH1 + r0 * 528 + col * 4)       = make_float2(h00, h01);
            *(float2*)(sH1 + (r0 + 8) * 528 + col * 4) = make_float2(h10, h11);
            acc[t][j][0] = acc[t][j][1] = acc[t][j][2] = acc[t][j][3] = 0.0f;
        }
    }

    // ---------------- layer 2: K=128, 8 chunks (h1 via ldsm from sH1) ----------------
    for (int c = 0; c < 8; ++c) {
        const uint32_t boffs = (uint32_t)((c & 1) * 10240);
        CP_WAIT0();
        __syncthreads();              // first iter: also orders sH1 stores before ldsm
        if (c + 1 < 8) {
            const float* bp = W2t + row * 128 + (c + 1) * 16 + half * 8;
            cpa16(aB + (boffs ^ 10240) + stg, bp);
            cpa16(aB + (boffs ^ 10240) + stg + 16, bp + 4);
        }
        CP_COMMIT();

        const int k0 = c * 16;
        uint32_t a00[4], a01[4], a10[4], a11[4];
        ldsm4(a00, aH1 + hoff0 + k0 * 4);
        ldsm4(a01, aH1 + hoff0 + k0 * 4 + 32);
        ldsm4(a10, aH1 + hoff1 + k0 * 4);
        ldsm4(a11, aH1 + hoff1 + k0 * 4 + 32);
        #pragma unroll
        for (int p = 0; p < 4; ++p) {
            uint32_t b[4], b2[4];
            ldsm4(b,  aB + boffs + boffW + p * 1280);
            ldsm4(b2, aB + boffs + boffW + p * 1280 + 32);
            mma_tf32(acc[0][2 * p],     a00, b[0],  b[1]);
            mma_tf32(acc[0][2 * p + 1], a00, b[2],  b[3]);
            mma_tf32(acc[1][2 * p],     a10, b[0],  b[1]);
            mma_tf32(acc[1][2 * p + 1], a10, b[2],  b[3]);
            mma_tf32(acc[0][2 * p],     a01, b2[0], b2[1]);
            mma_tf32(acc[0][2 * p + 1], a01, b2[2], b2[3]);
            mma_tf32(acc[1][2 * p],     a11, b2[0], b2[1]);
            mma_tf32(acc[1][2 * p + 1], a11, b2[2], b2[3]);
        }
    }

    // ---------------- epilogue 2: bias + softplus + store (+ scatter) ----------------
    #pragma unroll
    for (int t = 0; t < 2; ++t) {
        const int r0l = 32 * mg + 16 * t + (l >> 2);
        const int r0 = m0 + r0l;
        const int db0 = EDGE ? base[r0l * 4 + 0] : 0;
        const int db1 = EDGE ? base[(r0l + 8) * 4 + 0] : 0;
        #pragma unroll
        for (int j = 0; j < 8; ++j) {
            int col = 64 * ng + j * 8 + 2 * (l & 3);
            float bb0 = __ldg(b2 + col), bb1 = __ldg(b2 + col + 1);
            float o00 = softplusf(acc[t][j][0] + bb0);
            float o01 = softplusf(acc[t][j][1] + bb1);
            float o10 = softplusf(acc[t][j][2] + bb0);
            float o11 = softplusf(acc[t][j][3] + bb1);
            if (r0 < M) {
                *(float2*)(outp + (size_t)r0 * HH + col) = make_float2(o00, o01);
                if (EDGE) {
                    atomicAdd(&d_e_sum[db0 + col], o00);
                    atomicAdd(&d_e_sum[db0 + col + 1], o01);
                }
            }
            if (r0 + 8 < M) {
                *(float2*)(outp + (size_t)(r0 + 8) * HH + col) = make_float2(o10, o11);
                if (EDGE) {
                    atomicAdd(&d_e_sum[db1 + col], o10);
                    atomicAdd(&d_e_sum[db1 + col + 1], o11);
                }
            }
        }
        if (EDGE && ng == 0 && (l & 3) == 0) {   // rows shared by 2 warps: count once
            if (r0 < M)     atomicAdd(&d_cnt[db0 >> 7], 1.0f);
            if (r0 + 8 < M) atomicAdd(&d_cnt[db1 >> 7], 1.0f);
        }
    }
}

// ---------------- per-graph partial reductions (grid: GG x NSPLIT) ----------------
static constexpr int NSPLIT = 8;
__global__ void graph_partial_kernel(const float* __restrict__ xnew) {
    int g = blockIdx.x;
    int n = threadIdx.x;
    int s = d_start[g], e = d_start[g + 1];
    int len = e - s;
    int per = (len + NSPLIT - 1) / NSPLIT;
    int ls = s + blockIdx.y * per;
    int le = min(ls + per, e);
    if (ls >= le) return;
    float se = 0.0f, sv = 0.0f;
    for (int v = ls; v < le; ++v) {
        se += d_e_sum[v * HH + n];
        sv += xnew[(size_t)v * HH + n];
    }
    atomicAdd(&d_e_mean[g * HH + n], se);
    atomicAdd(&d_v_mean[g * HH + n], sv);
    __shared__ float red[HH];
    float sc = 0.0f;
    for (int v = ls + n; v < le; v += HH) sc += d_cnt[v];
    red[n] = sc;
    __syncthreads();
    for (int off = 64; off > 0; off >>= 1) {
        if (n < off) red[n] += red[n + off];
        __syncthreads();
    }
    if (n == 0) atomicAdd(&d_gecnt[g], red[0]);
}

__global__ void global_mlp_kernel(const float* __restrict__ u,
                                  const float* __restrict__ W1, const float* __restrict__ b1,
                                  const float* __restrict__ W2, const float* __restrict__ b2,
                                  float* __restrict__ out_u) {
    __shared__ float in[3 * HH];
    __shared__ float h1s[HH];
    int g = blockIdx.x, n = threadIdx.x;
    float ec = fmaxf(d_gecnt[g], 1.0f);
    float vc = fmaxf((float)(d_start[g + 1] - d_start[g]), 1.0f);
    in[n]          = u[g * HH + n];
    in[HH + n]     = d_e_mean[g * HH + n] / ec;
    in[2 * HH + n] = d_v_mean[g * HH + n] / vc;
    __syncthreads();
    float a = b1[n];
    for (int k = 0; k < 3 * HH; ++k) a += in[k] * W1[k * HH + n];
    h1s[n] = softplusf(a);
    __syncthreads();
    float o = b2[n];
    for (int k = 0; k < HH; ++k) o += h1s[k] * W2[k * HH + n];
    out_u[g * HH + n] = softplusf(o);
}

// ---------------- launch ----------------
extern "C" void kernel_launch(void* const* d_in, const int* in_sizes, int n_in,
                              void* d_out, int out_size) {
    const float* x     = (const float*)d_in[0];
    const int*   ei    = (const int*)d_in[1];
    const float* ea    = (const float*)d_in[2];
    const float* u     = (const float*)d_in[3];
    const int*   batch = (const int*)d_in[4];
    const float* We1 = (const float*)d_in[5];
    const float* be1 = (const float*)d_in[6];
    const float* We2 = (const float*)d_in[7];
    const float* be2 = (const float*)d_in[8];
    const float* Wv1 = (const float*)d_in[9];
    const float* bv1 = (const float*)d_in[10];
    const float* Wv2 = (const float*)d_in[11];
    const float* bv2 = (const float*)d_in[12];
    const float* Wu1 = (const float*)d_in[13];
    const float* bu1 = (const float*)d_in[14];
    const float* Wu2 = (const float*)d_in[15];
    const float* bu2 = (const float*)d_in[16];

    float* out   = (float*)d_out;
    float* out_x = out;
    float* out_e = out + (size_t)NN * HH;
    float* out_u = out + (size_t)(NN + EE) * HH;

    float *pW1t, *pW2t, *pV1t, *pV2t;
    cudaGetSymbolAddress((void**)&pW1t, d_W1t);
    cudaGetSymbolAddress((void**)&pW2t, d_W2t);
    cudaGetSymbolAddress((void**)&pV1t, d_V1t);
    cudaGetSymbolAddress((void**)&pV2t, d_V2t);

    const int SMEM = 111104;
    cudaFuncSetAttribute(mlp2_mma<4, true>,  cudaFuncAttributeMaxDynamicSharedMemorySize, SMEM);
    cudaFuncSetAttribute(mlp2_mma<3, false>, cudaFuncAttributeMaxDynamicSharedMemorySize, SMEM);

    detect_kernel<<<1, 32>>>(ei);
    convert_zero_kernel<<<(NN * HH + 255) / 256, 256>>>(ei, batch);
    prep_all_kernel<<<(4 * HH * HH + 255) / 256, 256>>>(We1, We2, Wv1, Wv2);

    // edge MLP + scatter (4th launch: ncu capture window)
    mlp2_mma<4, true><<<(EE + 127) / 128, TPB, SMEM>>>(
        x, x, ea, u, pW1t, be1, pW2t, be2, out_e, EE);

    // node MLP (e_aggr on the fly)
    mlp2_mma<3, false><<<(NN + 127) / 128, TPB, SMEM>>>(
        x, nullptr, u, nullptr, pV1t, bv1, pV2t, bv2, out_x, NN);

    seg_starts_kernel<<<(NN + 255) / 256, 256>>>();
    graph_partial_kernel<<<dim3(GG, NSPLIT), HH>>>(out_x);
    global_mlp_kernel<<<GG, HH>>>(u, Wu1, bu1, Wu2, bu2, out_u);
}